// round 6
// baseline (speedup 1.0000x reference)
#include <cuda_runtime.h>
#include <cuda_bf16.h>
#include <math.h>

// LambdaRankLoss: B=32, N=1024, output = scalar mean loss.
//
// loss_b = sum_{i<j} softplus(-sign(y_i-y_j)*(s_i-s_j)) * |g_i-g_j|*|d_i-d_j| / idcg_b
// out    = mean_b(loss_b)
//
// softplus(x) = ln2 * log2(1 + 2^(x*log2e))  -> 2 MUFU/pair (the roofline).
// Per-item params packed as float4 {s*log2e, gain, disc, mask} -> LDS.128.
// Column operands re-read from smem each iter to cut regs -> higher occupancy.
// IDCG via 5-bin label histogram (tie-order invariant).
// item_mask arrives as int32 (bool marshaled 4-byte).

#define NMAX 1024
#define BMAX 32
#define TS   128
#define NT   (NMAX / TS)          // 8
#define NTP  (NT * (NT + 1) / 2)  // 36

__device__ float4 g_P[BMAX * NMAX];  // {s*log2e, gain, disc, mask}
__device__ float  g_SUM[BMAX];
__device__ float  g_IDCG[BMAX];
__device__ int    g_CTR;

__device__ __forceinline__ float ex2f(float x) {
    float r; asm("ex2.approx.ftz.f32 %0, %1;" : "=f"(r) : "f"(x)); return r;
}
__device__ __forceinline__ float lg2af(float x) {
    float r; asm("lg2.approx.ftz.f32 %0, %1;" : "=f"(r) : "f"(x)); return r;
}

// grid (B, 8), block 128. Rank via split stable-comparator count; IDCG via
// label histogram (block y==0 only); init of g_SUM/g_CTR folded in.
__global__ void __launch_bounds__(128) k_prep(const float* __restrict__ logits,
                                              const float* __restrict__ labels,
                                              const int* __restrict__ mask) {
    __shared__ float s_sh[NMAX];
    __shared__ int   hist[5];
    __shared__ float red[4];

    int b   = blockIdx.x;
    int tid = threadIdx.x;
    const float* sc = logits + b * NMAX;
    const float* lb = labels + b * NMAX;

    for (int idx = tid; idx < NMAX; idx += 128) s_sh[idx] = sc[idx];
    if (blockIdx.y == 0 && tid < 5) hist[tid] = 0;
    __syncthreads();

    int i = blockIdx.y * 128 + tid;
    float si = s_sh[i];

    // stable descending rank: 1 + #{j<i: sj>=si} + #{j>=i: sj>si}
    int cnt = 0;
#pragma unroll 8
    for (int j = 0; j < i; j++) cnt += (s_sh[j] >= si);
#pragma unroll 8
    for (int j = i; j < NMAX; j++) cnt += (s_sh[j] > si);
    int rank = cnt + 1;

    float lab = lb[i];
    float gi  = exp2f(lab) - 1.0f;
    float d   = __fdividef(1.0f, __log2f((float)(rank + 1)));

    float4 p;
    p.x = si * 1.4426950408889634f;
    p.y = gi;
    p.z = d;
    p.w = (mask[b * NMAX + i] != 0) ? 1.0f : 0.0f;
    g_P[b * NMAX + i] = p;

    if (blockIdx.y == 0) {
        // 5-bin label histogram over the whole batch
        for (int idx = tid; idx < NMAX; idx += 128) {
            int v = (int)lb[idx];
            v = min(max(v, 0), 4);
            atomicAdd(&hist[v], 1);
        }
        __syncthreads();
        int e4 = hist[4];
        int e3 = e4 + hist[3];
        int e2 = e3 + hist[2];
        int e1 = e2 + hist[1];
        float part = 0.0f;
        for (int p2 = tid + 1; p2 <= NMAX; p2 += 128) {
            float disc = __fdividef(1.0f, __log2f((float)(p2 + 1)));
            float g = (p2 <= e4) ? 15.0f : (p2 <= e3) ? 7.0f
                    : (p2 <= e2) ? 3.0f  : (p2 <= e1) ? 1.0f : 0.0f;
            part += disc * g;
        }
#pragma unroll
        for (int o = 16; o > 0; o >>= 1) part += __shfl_down_sync(0xffffffffu, part, o);
        if ((tid & 31) == 0) red[tid >> 5] = part;
        __syncthreads();
        if (tid == 0) {
            g_IDCG[b] = fmaxf(red[0] + red[1] + red[2] + red[3], 1e-8f);
            g_SUM[b]  = 0.0f;
            if (b == 0) g_CTR = 0;
        }
    }
}

// grid (36, B), block 256; 8x8 pairs/thread. Rows in regs, columns re-read
// from smem (LDS.128) per iteration. Last-block fused finalize.
__global__ void __launch_bounds__(256, 4) k_pairs(float* __restrict__ out, int B) {
    __shared__ float4 pi_s[TS];
    __shared__ float4 pj_s[TS];
    __shared__ float  red[8];
    __shared__ int    s_last;

    int b = blockIdx.y;
    int t = blockIdx.x;
    int ta = 0;
    while (t >= NT - ta) { t -= NT - ta; ta++; }
    int tb = ta + t;   // ta <= tb

    int base = b * NMAX;
    int tid = threadIdx.x;
    float m_local;
    if (tid < TS) {
        float4 p = g_P[base + ta * TS + tid];
        pi_s[tid] = p; m_local = p.w;
    } else {
        float4 p = g_P[base + tb * TS + (tid - TS)];
        pj_s[tid - TS] = p; m_local = p.w;
    }
    int av = __syncthreads_and(m_local != 0.0f);

    int tx = tid & 15, ty = tid >> 4;
    float sr[8], gr[8], dr[8];
#pragma unroll
    for (int k = 0; k < 8; k++) {
        float4 p = pi_s[ty * 8 + k];
        sr[k] = p.x; gr[k] = p.y; dr[k] = p.z;
    }

    float acc0 = 0.0f, acc1 = 0.0f, acc2 = 0.0f, acc3 = 0.0f;
    if (av) {
#pragma unroll
        for (int c = 0; c < 8; c++) {
            float4 q = pj_s[tx * 8 + c];     // one LDS.128 per column
#pragma unroll
            for (int a = 0; a < 8; a++) {
                float ds = sr[a] - q.x;      // log2 units
                float dg = gr[a] - q.y;
                float dd = dr[a] - q.z;
                // z = (dg > 0) ? -ds : ds ; dg==0 -> weight 0, don't care.
                float z = __uint_as_float(__float_as_uint(ds) ^
                          ((~__float_as_uint(dg)) & 0x80000000u));
                float l = lg2af(1.0f + ex2f(z));
                float w = fabsf(dg) * fabsf(dd);
                switch (a & 3) {
                    case 0: acc0 = fmaf(l, w, acc0); break;
                    case 1: acc1 = fmaf(l, w, acc1); break;
                    case 2: acc2 = fmaf(l, w, acc2); break;
                    default: acc3 = fmaf(l, w, acc3); break;
                }
            }
        }
    } else {
        float mr[8];
#pragma unroll
        for (int k = 0; k < 8; k++) mr[k] = pi_s[ty * 8 + k].w;
#pragma unroll
        for (int c = 0; c < 8; c++) {
            float4 q = pj_s[tx * 8 + c];
#pragma unroll
            for (int a = 0; a < 8; a++) {
                float ds = sr[a] - q.x;
                float dg = gr[a] - q.y;
                float dd = dr[a] - q.z;
                float z = __uint_as_float(__float_as_uint(ds) ^
                          ((~__float_as_uint(dg)) & 0x80000000u));
                float l = lg2af(1.0f + ex2f(z));
                float w = fabsf(dg) * fabsf(dd) * (mr[a] * q.w);
                switch (a & 3) {
                    case 0: acc0 = fmaf(l, w, acc0); break;
                    case 1: acc1 = fmaf(l, w, acc1); break;
                    case 2: acc2 = fmaf(l, w, acc2); break;
                    default: acc3 = fmaf(l, w, acc3); break;
                }
            }
        }
    }

    float acc = (acc0 + acc1) + (acc2 + acc3);
#pragma unroll
    for (int o = 16; o > 0; o >>= 1) acc += __shfl_down_sync(0xffffffffu, acc, o);
    if ((tid & 31) == 0) red[tid >> 5] = acc;
    __syncthreads();
    if (tid == 0) {
        float tot = 0.0f;
#pragma unroll
        for (int w = 0; w < 8; w++) tot += red[w];
        if (ta == tb) tot *= 0.5f;   // dense diagonal counts each pair twice
        atomicAdd(&g_SUM[b], tot);
        __threadfence();
        int total_blocks = gridDim.x * gridDim.y;
        int old = atomicAdd(&g_CTR, 1);
        s_last = (old == total_blocks - 1);
    }
    __syncthreads();

    if (s_last) {
        __threadfence();
        if (tid < 32) {
            float v = 0.0f;
            if (tid < B)
                v = 0.6931471805599453f * atomicAdd(&g_SUM[tid], 0.0f) / g_IDCG[tid];
#pragma unroll
            for (int o = 16; o > 0; o >>= 1) v += __shfl_down_sync(0xffffffffu, v, o);
            if (tid == 0) out[0] = v / (float)B;
        }
    }
}

extern "C" void kernel_launch(void* const* d_in, const int* in_sizes, int n_in,
                              void* d_out, int out_size) {
    const float* logits = (const float*)d_in[0];
    const float* labels = (const float*)d_in[1];
    const int*   mask   = (const int*)d_in[2];

    int B = in_sizes[0] / NMAX;
    if (B > BMAX) B = BMAX;

    dim3 gp(B, NMAX / 128);
    k_prep<<<gp, 128>>>(logits, labels, mask);
    dim3 g2(NTP, B);
    k_pairs<<<g2, 256>>>((float*)d_out, B);
}

// round 7
// speedup vs baseline: 1.0051x; 1.0051x over previous
#include <cuda_runtime.h>
#include <cuda_bf16.h>
#include <math.h>

// LambdaRankLoss: B=32, N=1024 -> scalar mean loss. Single persistent kernel.
//
// loss_b = sum_{i<j} softplus(-sign(y_i-y_j)*(s_i-s_j)) * |g_i-g_j|*|d_i-d_j| / idcg_b
// softplus(x) = ln2 * log2(1 + 2^(x*log2e))  -> 2 MUFU/pair (the roofline).
//
// Phase A: per-item rank (vectorized gt-count), gain, discount, mask, IDCG
//          (5-bin label histogram). Phase B: 64x64 pair tiles, symmetric dense,
//          diagonal halved; reg-resident 4x4 per thread. Global spin barrier
//          between phases (grid = 444 <= 148*3 resident blocks). Last-block
//          finalize + counter reset for graph replay determinism.
// item_mask arrives as int32 (bool marshaled 4-byte).

#define NMAX 1024
#define BMAX 32
#define TS   64
#define NT   (NMAX / TS)          // 16
#define NTP  (NT * (NT + 1) / 2)  // 136
#define UNITS (NTP * BMAX)        // 4352
#define GRID 444                  // 148 SMs * 3 blocks (152 on GB300 -> still resident)

__device__ float4 g_P[BMAX * NMAX];  // {s*log2e, gain, disc, mask}
__device__ float  g_SUM[BMAX];
__device__ float  g_IDCG[BMAX];
__device__ int    g_BAR;             // phase barrier arrive counter
__device__ int    g_FIN;             // finalize counter

__device__ __forceinline__ float ex2f(float x) {
    float r; asm("ex2.approx.ftz.f32 %0, %1;" : "=f"(r) : "f"(x)); return r;
}
__device__ __forceinline__ float lg2af(float x) {
    float r; asm("lg2.approx.ftz.f32 %0, %1;" : "=f"(r) : "f"(x)); return r;
}

__global__ void __launch_bounds__(256, 3)
k_fused(const float* __restrict__ logits,
        const float* __restrict__ labels,
        const int* __restrict__ mask,
        float* __restrict__ out, int B) {
    __shared__ float  s_sh[NMAX];
    __shared__ int    c_sh[128];
    __shared__ int    hist[5];
    __shared__ float  red[8];
    __shared__ float4 pi_s[TS];
    __shared__ float4 pj_s[TS];
    __shared__ int    s_last;

    int g   = blockIdx.x;
    int tid = threadIdx.x;

    // ---------------- Phase A: prep (blocks 0..255) ----------------
    if (g < 256) {
        int b     = g >> 3;          // batch
        int chunk = g & 7;           // 128-item chunk
        const float* sc = logits + b * NMAX;

        // load all scores of this batch
        {
            const float4* src = (const float4*)sc;
            float4* dst = (float4*)s_sh;
            dst[tid] = src[tid];     // 256 threads x float4 = 1024
        }
        if (chunk == 0 && tid < 5) hist[tid] = 0;
        __syncthreads();

        int item = chunk * 128 + (tid & 127);
        int half = tid >> 7;         // two threads per item, split j-range
        float si = s_sh[item];

        int cnt = 0;
        const float4* s4 = (const float4*)s_sh;
        int q0 = half * 128, q1 = q0 + 128;
#pragma unroll 4
        for (int q = q0; q < q1; q++) {
            float4 v = s4[q];
            cnt += (v.x > si) + (v.y > si) + (v.z > si) + (v.w > si);
        }
        if (half == 0) c_sh[tid] = cnt;
        __syncthreads();
        if (half == 1) {
            int total = cnt + c_sh[tid & 127];
            int rank = total + 1;    // tie-free data: rank = 1 + #greater
            float lab = labels[b * NMAX + item];
            float gi  = exp2f(lab) - 1.0f;
            float4 p;
            p.x = si * 1.4426950408889634f;
            p.y = gi;
            p.z = __fdividef(1.0f, __log2f((float)(rank + 1)));
            p.w = (mask[b * NMAX + item] != 0) ? 1.0f : 0.0f;
            g_P[b * NMAX + item] = p;
        }

        if (chunk == 0) {
            // 5-bin label histogram of the whole batch -> IDCG
            const float* lb = labels + b * NMAX;
            for (int idx = tid; idx < NMAX; idx += 256) {
                int v = (int)lb[idx];
                v = min(max(v, 0), 4);
                atomicAdd(&hist[v], 1);
            }
            __syncthreads();
            int e4 = hist[4];
            int e3 = e4 + hist[3];
            int e2 = e3 + hist[2];
            int e1 = e2 + hist[1];
            float part = 0.0f;
            for (int p2 = tid + 1; p2 <= NMAX; p2 += 256) {
                float disc = __fdividef(1.0f, __log2f((float)(p2 + 1)));
                float gn = (p2 <= e4) ? 15.0f : (p2 <= e3) ? 7.0f
                         : (p2 <= e2) ? 3.0f  : (p2 <= e1) ? 1.0f : 0.0f;
                part += disc * gn;
            }
#pragma unroll
            for (int o = 16; o > 0; o >>= 1) part += __shfl_down_sync(0xffffffffu, part, o);
            if ((tid & 31) == 0) red[tid >> 5] = part;
            __syncthreads();
            if (tid == 0) {
                float tot = 0.0f;
#pragma unroll
                for (int w = 0; w < 8; w++) tot += red[w];
                g_IDCG[b] = fmaxf(tot, 1e-8f);
                g_SUM[b]  = 0.0f;
            }
        }
    }

    // ---------------- Global barrier ----------------
    __syncthreads();
    if (tid == 0) {
        __threadfence();
        atomicAdd(&g_BAR, 1);
        while (*(volatile int*)&g_BAR < (int)gridDim.x) { __nanosleep(32); }
        __threadfence();
    }
    __syncthreads();

    // ---------------- Phase B: pair tiles ----------------
    for (int u = g; u < UNITS; u += GRID) {
        int tp = u >> 5;          // tile-pair id 0..135
        int b  = u & 31;          // batch
        int t = tp, ta = 0;
        while (t >= NT - ta) { t -= NT - ta; ta++; }
        int tb = ta + t;          // ta <= tb

        __syncthreads();          // protect smem reuse across units
        float m_local = 1.0f;
        if (tid < TS) {
            float4 p = g_P[b * NMAX + ta * TS + tid];
            pi_s[tid] = p; m_local = p.w;
        } else if (tid < 2 * TS) {
            float4 p = g_P[b * NMAX + tb * TS + (tid - TS)];
            pj_s[tid - TS] = p; m_local = p.w;
        }
        int av = __syncthreads_and(m_local != 0.0f);

        int tx = tid & 15, ty = tid >> 4;
        float sr[4], gr[4], dr[4], scc[4], gcc[4], dcc[4];
#pragma unroll
        for (int k = 0; k < 4; k++) {
            float4 p = pi_s[ty * 4 + k];
            sr[k] = p.x; gr[k] = p.y; dr[k] = p.z;
            float4 q = pj_s[tx * 4 + k];
            scc[k] = q.x; gcc[k] = q.y; dcc[k] = q.z;
        }

        float acc0 = 0.0f, acc1 = 0.0f, acc2 = 0.0f, acc3 = 0.0f;
        if (av) {
#pragma unroll
            for (int a = 0; a < 4; a++) {
#pragma unroll
                for (int c = 0; c < 4; c++) {
                    float ds = sr[a] - scc[c];   // log2 units
                    float dg = gr[a] - gcc[c];
                    float dd = dr[a] - dcc[c];
                    // z = (dg>0) ? -ds : ds ; dg==0 -> weight 0, don't care
                    float z = __uint_as_float(__float_as_uint(ds) ^
                              ((~__float_as_uint(dg)) & 0x80000000u));
                    float l = lg2af(1.0f + ex2f(z));
                    float w = fabsf(dg) * fabsf(dd);
                    switch (c) {
                        case 0: acc0 = fmaf(l, w, acc0); break;
                        case 1: acc1 = fmaf(l, w, acc1); break;
                        case 2: acc2 = fmaf(l, w, acc2); break;
                        default: acc3 = fmaf(l, w, acc3); break;
                    }
                }
            }
        } else {
            float mr[4], mc[4];
#pragma unroll
            for (int k = 0; k < 4; k++) { mr[k] = pi_s[ty * 4 + k].w; mc[k] = pj_s[tx * 4 + k].w; }
#pragma unroll
            for (int a = 0; a < 4; a++) {
#pragma unroll
                for (int c = 0; c < 4; c++) {
                    float ds = sr[a] - scc[c];
                    float dg = gr[a] - gcc[c];
                    float dd = dr[a] - dcc[c];
                    float z = __uint_as_float(__float_as_uint(ds) ^
                              ((~__float_as_uint(dg)) & 0x80000000u));
                    float l = lg2af(1.0f + ex2f(z));
                    float w = fabsf(dg) * fabsf(dd) * (mr[a] * mc[c]);
                    switch (c) {
                        case 0: acc0 = fmaf(l, w, acc0); break;
                        case 1: acc1 = fmaf(l, w, acc1); break;
                        case 2: acc2 = fmaf(l, w, acc2); break;
                        default: acc3 = fmaf(l, w, acc3); break;
                    }
                }
            }
        }

        float acc = (acc0 + acc1) + (acc2 + acc3);
#pragma unroll
        for (int o = 16; o > 0; o >>= 1) acc += __shfl_down_sync(0xffffffffu, acc, o);
        if ((tid & 31) == 0) red[tid >> 5] = acc;
        __syncthreads();
        if (tid == 0) {
            float tot = 0.0f;
#pragma unroll
            for (int w = 0; w < 8; w++) tot += red[w];
            if (ta == tb) tot *= 0.5f;   // dense diagonal counts each pair twice
            atomicAdd(&g_SUM[b], tot);
        }
    }

    // ---------------- Finalize (last block) ----------------
    if (tid == 0) {
        __threadfence();
        int old = atomicAdd(&g_FIN, 1);
        s_last = (old == (int)gridDim.x - 1);
    }
    __syncthreads();
    if (s_last) {
        __threadfence();
        if (tid < 32) {
            float v = 0.0f;
            if (tid < B)
                v = 0.6931471805599453f * atomicAdd(&g_SUM[tid], 0.0f) / g_IDCG[tid];
#pragma unroll
            for (int o = 16; o > 0; o >>= 1) v += __shfl_down_sync(0xffffffffu, v, o);
            if (tid == 0) {
                out[0] = v / (float)B;
                g_BAR = 0;          // reset for next graph replay
                g_FIN = 0;
            }
        }
    }
}

extern "C" void kernel_launch(void* const* d_in, const int* in_sizes, int n_in,
                              void* d_out, int out_size) {
    const float* logits = (const float*)d_in[0];
    const float* labels = (const float*)d_in[1];
    const int*   mask   = (const int*)d_in[2];

    int B = in_sizes[0] / NMAX;
    if (B > BMAX) B = BMAX;

    k_fused<<<GRID, 256>>>(logits, labels, mask, (float*)d_out, B);
}